// round 1
// baseline (speedup 1.0000x reference)
#include <cuda_runtime.h>
#include <cuda_bf16.h>

#define Bsz 8
#define Ns  1024
#define Cs  512
#define HIDs 2048
#define Ms  (Bsz*Ns)

// ---------------- scratch (device globals; no allocations allowed) ----------
__device__ __align__(16) float g_xn [(size_t)Ms*Cs];        // LN output
__device__ __align__(16) float g_qkv[(size_t)Ms*3*Cs];      // qkv
__device__ __align__(16) float g_att[(size_t)Ms*Cs];        // attention output (pre-proj)
__device__ __align__(16) float g_h1 [(size_t)Ms*HIDs];      // fc1 output
__device__ __align__(16) float g_h2 [(size_t)Ms*HIDs];      // dwconv+gelu output

// ---------------- LayerNorm: one block (128 thr) per row of 512 -------------
__global__ void ln_k(const float* __restrict__ x, const float* __restrict__ g,
                     const float* __restrict__ beta, float* __restrict__ y)
{
    __shared__ float red[8];
    const int row = blockIdx.x, tid = threadIdx.x;  // 128 threads, 4 floats each
    float4 v = ((const float4*)(x + (size_t)row*Cs))[tid];
    float s = v.x+v.y+v.z+v.w;
    float q = v.x*v.x+v.y*v.y+v.z*v.z+v.w*v.w;
    #pragma unroll
    for (int o = 16; o; o >>= 1) {
        s += __shfl_xor_sync(0xffffffffu, s, o);
        q += __shfl_xor_sync(0xffffffffu, q, o);
    }
    const int w = tid >> 5;
    if ((tid & 31) == 0) { red[w] = s; red[4+w] = q; }
    __syncthreads();
    s = red[0]+red[1]+red[2]+red[3];
    q = red[4]+red[5]+red[6]+red[7];
    const float mu  = s * (1.f/Cs);
    const float var = q * (1.f/Cs) - mu*mu;
    const float rinv = rsqrtf(var + 1e-5f);
    float4 gg = ((const float4*)g)[tid];
    float4 bb = ((const float4*)beta)[tid];
    float4 o;
    o.x = (v.x-mu)*rinv*gg.x + bb.x;
    o.y = (v.y-mu)*rinv*gg.y + bb.y;
    o.z = (v.z-mu)*rinv*gg.z + bb.z;
    o.w = (v.w-mu)*rinv*gg.w + bb.w;
    ((float4*)(y + (size_t)row*Cs))[tid] = o;
}

// ---------------- NT GEMM: C[m,n] = sum_k A[m,k]*Bw[n,k] (+bias[n]) (+res[m,n])
// 128x128 block tile, BK=16, 256 threads, 8x8 microtile (split 4+4 for
// conflict-free float4 smem reads). M,N multiples of 128; K multiple of 16.
__global__ __launch_bounds__(256, 2) void gemm_nt(
    const float* __restrict__ A, const float* __restrict__ Bw,
    const float* __restrict__ bias, const float* __restrict__ res,
    float* __restrict__ C, int M, int N, int K)
{
    __shared__ __align__(16) float As[16][132];
    __shared__ __align__(16) float Bs[16][132];
    const int tid = threadIdx.x;
    const int tx = tid & 15, ty = tid >> 4;
    const int row0 = blockIdx.y * 128, col0 = blockIdx.x * 128;

    float acc[8][8];
    #pragma unroll
    for (int i = 0; i < 8; i++)
        #pragma unroll
        for (int j = 0; j < 8; j++) acc[i][j] = 0.f;

    const int lr  = tid >> 2;         // 0..63
    const int lc4 = (tid & 3) * 4;    // 0,4,8,12
    const float* Ap = A  + (size_t)(row0 + lr) * K + lc4;
    const float* Bp = Bw + (size_t)(col0 + lr) * K + lc4;

    for (int k0 = 0; k0 < K; k0 += 16) {
        #pragma unroll
        for (int i = 0; i < 2; i++) {
            const int r = lr + i*64;
            float4 va = *(const float4*)(Ap + k0 + (size_t)i*64*K);
            float4 vb = *(const float4*)(Bp + k0 + (size_t)i*64*K);
            As[lc4+0][r]=va.x; As[lc4+1][r]=va.y; As[lc4+2][r]=va.z; As[lc4+3][r]=va.w;
            Bs[lc4+0][r]=vb.x; Bs[lc4+1][r]=vb.y; Bs[lc4+2][r]=vb.z; Bs[lc4+3][r]=vb.w;
        }
        __syncthreads();
        #pragma unroll
        for (int k = 0; k < 16; k++) {
            float4 a0 = *(const float4*)&As[k][ty*4];
            float4 a1 = *(const float4*)&As[k][64 + ty*4];
            float4 b0 = *(const float4*)&Bs[k][tx*4];
            float4 b1 = *(const float4*)&Bs[k][64 + tx*4];
            float ra[8] = {a0.x,a0.y,a0.z,a0.w,a1.x,a1.y,a1.z,a1.w};
            float rb[8] = {b0.x,b0.y,b0.z,b0.w,b1.x,b1.y,b1.z,b1.w};
            #pragma unroll
            for (int i = 0; i < 8; i++)
                #pragma unroll
                for (int j = 0; j < 8; j++)
                    acc[i][j] = fmaf(ra[i], rb[j], acc[i][j]);
        }
        __syncthreads();
    }

    #pragma unroll
    for (int i = 0; i < 8; i++) {
        const int r = row0 + ((i < 4) ? (ty*4 + i) : (64 + ty*4 + i - 4));
        #pragma unroll
        for (int jj = 0; jj < 2; jj++) {
            const int c = col0 + jj*64 + tx*4;
            float4 o;
            o.x = acc[i][jj*4+0]; o.y = acc[i][jj*4+1];
            o.z = acc[i][jj*4+2]; o.w = acc[i][jj*4+3];
            if (bias) {
                float4 bv = *(const float4*)(bias + c);
                o.x += bv.x; o.y += bv.y; o.z += bv.z; o.w += bv.w;
            }
            if (res) {
                float4 rv = *(const float4*)(res + (size_t)r*N + c);
                o.x += rv.x; o.y += rv.y; o.z += rv.z; o.w += rv.w;
            }
            *(float4*)(C + (size_t)r*N + c) = o;
        }
    }
}

// ---------------- Flash attention: per (b,h, 32-query tile), KV tiles of 64 -
// qkv layout per row (1536): head h owns cols [h*192, h*192+192) = q|k|v (64 each).
__global__ __launch_bounds__(128) void flash_k(const float* __restrict__ qkv,
                                               float* __restrict__ out)
{
    __shared__ __align__(16) float Qs[32][64];
    __shared__ __align__(16) float KtPs[64][68];   // K^T during S; P tile after
    __shared__ __align__(16) float Vs[64][64];

    const int tid = threadIdx.x;
    const int tx = tid & 15, ty = tid >> 4;
    const int bh = blockIdx.y, b = bh >> 3, h = bh & 7;
    const int qi0 = blockIdx.x * 32;
    const float* base = qkv + (size_t)b * Ns * 1536 + h * 192;

    #pragma unroll
    for (int i = 0; i < 4; i++) {       // load Q tile (32x64)
        const int slot = tid + i * 128;
        const int r = slot >> 4, c4 = (slot & 15) * 4;
        *(float4*)&Qs[r][c4] = *(const float4*)(base + (size_t)(qi0 + r) * 1536 + c4);
    }

    float m_r[4], l_r[4], acc[4][4];
    #pragma unroll
    for (int i = 0; i < 4; i++) {
        m_r[i] = -1e30f; l_r[i] = 0.f;
        #pragma unroll
        for (int j = 0; j < 4; j++) acc[i][j] = 0.f;
    }

    for (int j0 = 0; j0 < Ns; j0 += 64) {
        __syncthreads();                 // prev PV done; also covers Q load (iter 0)
        #pragma unroll
        for (int i = 0; i < 8; i++) {    // load K (transposed) + V tiles (64x64)
            const int slot = tid + i * 128;
            const int r = slot >> 4, c4 = (slot & 15) * 4;
            const float* krow = base + (size_t)(j0 + r) * 1536 + 64;
            float4 kv = *(const float4*)(krow + c4);
            KtPs[c4+0][r] = kv.x; KtPs[c4+1][r] = kv.y;
            KtPs[c4+2][r] = kv.z; KtPs[c4+3][r] = kv.w;
            *(float4*)&Vs[r][c4] = *(const float4*)(krow + 64 + c4);
        }
        __syncthreads();

        float s[4][4];
        #pragma unroll
        for (int i = 0; i < 4; i++)
            #pragma unroll
            for (int j = 0; j < 4; j++) s[i][j] = 0.f;
        #pragma unroll 8
        for (int dk = 0; dk < 64; dk++) {
            float4 bq = *(const float4*)&KtPs[dk][tx*4];
            float aq[4];
            #pragma unroll
            for (int i = 0; i < 4; i++) aq[i] = Qs[ty*4+i][dk];
            #pragma unroll
            for (int i = 0; i < 4; i++) {
                s[i][0] = fmaf(aq[i], bq.x, s[i][0]);
                s[i][1] = fmaf(aq[i], bq.y, s[i][1]);
                s[i][2] = fmaf(aq[i], bq.z, s[i][2]);
                s[i][3] = fmaf(aq[i], bq.w, s[i][3]);
            }
        }

        // online softmax update (rows reduced across the 16 tx lanes)
        #pragma unroll
        for (int i = 0; i < 4; i++) {
            float mloc = -1e30f;
            #pragma unroll
            for (int j = 0; j < 4; j++) { s[i][j] *= 0.125f; mloc = fmaxf(mloc, s[i][j]); }
            #pragma unroll
            for (int o = 8; o; o >>= 1) mloc = fmaxf(mloc, __shfl_xor_sync(0xffffffffu, mloc, o));
            const float mnew = fmaxf(m_r[i], mloc);
            const float alpha = __expf(m_r[i] - mnew);
            m_r[i] = mnew;
            float ls = 0.f;
            #pragma unroll
            for (int j = 0; j < 4; j++) { s[i][j] = __expf(s[i][j] - mnew); ls += s[i][j]; }
            #pragma unroll
            for (int o = 8; o; o >>= 1) ls += __shfl_xor_sync(0xffffffffu, ls, o);
            l_r[i] = l_r[i] * alpha + ls;
            #pragma unroll
            for (int j = 0; j < 4; j++) acc[i][j] *= alpha;
        }

        __syncthreads();                 // everyone done reading K^T
        float* Ps = &KtPs[0][0];         // reuse as P[32][64]
        #pragma unroll
        for (int i = 0; i < 4; i++)
            *(float4*)&Ps[(ty*4+i)*64 + tx*4] = make_float4(s[i][0], s[i][1], s[i][2], s[i][3]);
        __syncthreads();

        #pragma unroll 8
        for (int kj = 0; kj < 64; kj++) {
            float4 vv = *(const float4*)&Vs[kj][tx*4];
            float pv[4];
            #pragma unroll
            for (int i = 0; i < 4; i++) pv[i] = Ps[(ty*4+i)*64 + kj];
            #pragma unroll
            for (int i = 0; i < 4; i++) {
                acc[i][0] = fmaf(pv[i], vv.x, acc[i][0]);
                acc[i][1] = fmaf(pv[i], vv.y, acc[i][1]);
                acc[i][2] = fmaf(pv[i], vv.z, acc[i][2]);
                acc[i][3] = fmaf(pv[i], vv.w, acc[i][3]);
            }
        }
    }

    #pragma unroll
    for (int i = 0; i < 4; i++) {
        const float inv = 1.f / l_r[i];
        float4 o = make_float4(acc[i][0]*inv, acc[i][1]*inv, acc[i][2]*inv, acc[i][3]*inv);
        *(float4*)(out + (size_t)(b*Ns + qi0 + ty*4 + i) * Cs + h*64 + tx*4) = o;
    }
}

// ---------------- depthwise 3x3 conv + bias + exact GELU --------------------
__global__ void dwconv_gelu_k(const float* __restrict__ hin, const float* __restrict__ w,
                              const float* __restrict__ bias, float* __restrict__ out)
{
    const int bn = blockIdx.x;
    const int b = bn >> 10, n = bn & 1023;
    const int y = n >> 5, x = n & 31;
    const int tid = threadIdx.x;     // 256 threads
    #pragma unroll
    for (int gidx = 0; gidx < 2; gidx++) {
        const int c = (tid + gidx*256) * 4;
        float4 acc = *(const float4*)(bias + c);
        #pragma unroll
        for (int dy = -1; dy <= 1; dy++) {
            const int yy = y + dy;
            if ((unsigned)yy >= 32u) continue;
            #pragma unroll
            for (int dx = -1; dx <= 1; dx++) {
                const int xx = x + dx;
                if ((unsigned)xx >= 32u) continue;
                const float* hp = hin + ((size_t)(b << 10) + (yy << 5) + xx) * HIDs + c;
                float4 hv = *(const float4*)hp;
                const int t = (dy+1)*3 + (dx+1);
                acc.x = fmaf(hv.x, w[(c+0)*9 + t], acc.x);
                acc.y = fmaf(hv.y, w[(c+1)*9 + t], acc.y);
                acc.z = fmaf(hv.z, w[(c+2)*9 + t], acc.z);
                acc.w = fmaf(hv.w, w[(c+3)*9 + t], acc.w);
            }
        }
        float4 o;
        o.x = 0.5f*acc.x*(1.f + erff(acc.x*0.70710678118654752f));
        o.y = 0.5f*acc.y*(1.f + erff(acc.y*0.70710678118654752f));
        o.z = 0.5f*acc.z*(1.f + erff(acc.z*0.70710678118654752f));
        o.w = 0.5f*acc.w*(1.f + erff(acc.w*0.70710678118654752f));
        *(float4*)(out + (size_t)bn*HIDs + c) = o;
    }
}

// ---------------- launch ----------------------------------------------------
extern "C" void kernel_launch(void* const* d_in, const int* in_sizes, int n_in,
                              void* d_out, int out_size)
{
    const float* x      = (const float*)d_in[0];
    const float* ln1_g  = (const float*)d_in[1];
    const float* ln1_b  = (const float*)d_in[2];
    const float* qkv_w  = (const float*)d_in[3];
    const float* proj_w = (const float*)d_in[4];
    const float* proj_b = (const float*)d_in[5];
    const float* ln2_g  = (const float*)d_in[6];
    const float* ln2_b  = (const float*)d_in[7];
    const float* fc1_w  = (const float*)d_in[8];
    const float* fc1_b  = (const float*)d_in[9];
    const float* dw_w   = (const float*)d_in[10];
    const float* dw_b   = (const float*)d_in[11];
    const float* fc2_w  = (const float*)d_in[12];
    const float* fc2_b  = (const float*)d_in[13];
    float* out = (float*)d_out;

    float *xn, *qkv, *att, *h1, *h2;
    cudaGetSymbolAddress((void**)&xn,  g_xn);
    cudaGetSymbolAddress((void**)&qkv, g_qkv);
    cudaGetSymbolAddress((void**)&att, g_att);
    cudaGetSymbolAddress((void**)&h1,  g_h1);
    cudaGetSymbolAddress((void**)&h2,  g_h2);

    // x1 (post-attention residual) lives in d_out; final result overwrites it.
    ln_k<<<Ms, 128>>>(x, ln1_g, ln1_b, xn);
    gemm_nt<<<dim3(1536/128, Ms/128), 256>>>(xn, qkv_w, nullptr, nullptr, qkv, Ms, 1536, Cs);
    flash_k<<<dim3(Ns/32, Bsz*8), 128>>>(qkv, att);
    gemm_nt<<<dim3(Cs/128, Ms/128), 256>>>(att, proj_w, proj_b, x, out, Ms, Cs, Cs);
    ln_k<<<Ms, 128>>>(out, ln2_g, ln2_b, xn);
    gemm_nt<<<dim3(HIDs/128, Ms/128), 256>>>(xn, fc1_w, fc1_b, nullptr, h1, Ms, HIDs, Cs);
    dwconv_gelu_k<<<Ms, 256>>>(h1, dw_w, dw_b, h2);
    gemm_nt<<<dim3(Cs/128, Ms/128), 256>>>(h2, fc2_w, fc2_b, out, out, Ms, Cs, HIDs);
}

// round 6
// speedup vs baseline: 1.7840x; 1.7840x over previous
#include <cuda_runtime.h>
#include <cuda_bf16.h>
#include <cstdint>

#define Bsz 8
#define Ns  1024
#define Cs  512
#define HIDs 2048
#define Ms  (Bsz*Ns)

// ---------------- scratch (device globals; no allocations allowed) ----------
__device__ __align__(16) float g_xn [(size_t)Ms*Cs];        // LN output
__device__ __align__(16) float g_qkv[(size_t)Ms*3*Cs];      // qkv
__device__ __align__(16) float g_att[(size_t)Ms*Cs];        // attention output (pre-proj)
__device__ __align__(16) float g_h1 [(size_t)Ms*HIDs];      // fc1 output
__device__ __align__(16) float g_h2 [(size_t)Ms*HIDs];      // dwconv+gelu output

// ======================= PTX helpers (arch-neutral) =========================
__device__ __forceinline__ uint32_t smem_u32(const void* p) {
    uint32_t a;
    asm("{ .reg .u64 t; cvta.to.shared.u64 t, %1; cvt.u32.u64 %0, t; }" : "=r"(a) : "l"(p));
    return a;
}

// round-to-nearest fp32 -> tf32 (low 13 mantissa bits zeroed), store float4
__device__ __forceinline__ void st4_tf32(uint32_t saddr, float4 v)
{
    uint32_t a, b, c, d;
    asm("cvt.rna.tf32.f32 %0, %1;" : "=r"(a) : "f"(v.x));
    asm("cvt.rna.tf32.f32 %0, %1;" : "=r"(b) : "f"(v.y));
    asm("cvt.rna.tf32.f32 %0, %1;" : "=r"(c) : "f"(v.z));
    asm("cvt.rna.tf32.f32 %0, %1;" : "=r"(d) : "f"(v.w));
    asm volatile("st.shared.v4.b32 [%0], {%1, %2, %3, %4};"
        :: "r"(saddr), "r"(a), "r"(b), "r"(c), "r"(d) : "memory");
}

__device__ __forceinline__ void ldsm_x4(uint32_t* r, uint32_t addr)
{
    asm volatile("ldmatrix.sync.aligned.m8n8.x4.shared.b16 {%0,%1,%2,%3}, [%4];"
        : "=r"(r[0]), "=r"(r[1]), "=r"(r[2]), "=r"(r[3]) : "r"(addr));
}
__device__ __forceinline__ void ldsm_x2(uint32_t* r, uint32_t addr)
{
    asm volatile("ldmatrix.sync.aligned.m8n8.x2.shared.b16 {%0,%1}, [%2];"
        : "=r"(r[0]), "=r"(r[1]) : "r"(addr));
}

__device__ __forceinline__ void mma_tf32(float* c, const uint32_t* a, const uint32_t* b)
{
    asm volatile("mma.sync.aligned.m16n8k8.row.col.f32.tf32.tf32.f32 "
        "{%0,%1,%2,%3}, {%4,%5,%6,%7}, {%8,%9}, {%0,%1,%2,%3};"
        : "+f"(c[0]), "+f"(c[1]), "+f"(c[2]), "+f"(c[3])
        : "r"(a[0]), "r"(a[1]), "r"(a[2]), "r"(a[3]), "r"(b[0]), "r"(b[1]));
}

// ======================= mma.sync tf32 NT GEMM ==============================
// C[m,n] = sum_k A[m,k]*Bw[n,k] (+bias[n]) (+res[m,n]); both operands K-major.
// Block tile 128x128, BK=32. 8 warps in 2(m) x 4(n) grid; warp tile 64x32 =
// 4x4 grid of m16n8k8 MMAs over 4 K-steps per chunk. Reg-staged double buffer.
#define BK     32
#define LDSW   36                       // smem row stride (floats): 32 + 4 pad
#define TILE_F (128*LDSW)               // floats per A or B tile
#define GSMEM  (4*TILE_F*4)             // 2 buffers x (A+B) = 73728 bytes

__global__ __launch_bounds__(256) void gemm_mma(
    const float* __restrict__ A, const float* __restrict__ Bw,
    const float* __restrict__ bias, const float* __restrict__ res,
    float* __restrict__ C, int M, int N, int K)
{
    extern __shared__ float sm[];
    const int tid  = threadIdx.x;
    const int lane = tid & 31;
    const int w    = tid >> 5;
    const int wm   = w >> 2;            // 0..1  (64 rows each)
    const int wn   = w & 3;             // 0..3  (32 cols each)
    const int row0 = blockIdx.y * 128, col0 = blockIdx.x * 128;

    // ---- gmem staging mapping: 8 threads per row, rows (tid>>3) + 32*i ----
    const int lr = tid >> 3;            // 0..31
    const int lj = tid & 7;             // float4 index 0..7 within BK=32
    const float* Ag = A  + (size_t)(row0 + lr) * K + lj * 4;
    const float* Bg = Bw + (size_t)(col0 + lr) * K + lj * 4;

    const uint32_t smem0 = smem_u32(sm);
    // sts byte offset within a tile for (row lr+32i, col 4*lj)
    const uint32_t sts_off = (uint32_t)(lr * LDSW + lj * 4) * 4;

    // ---- ldmatrix source addresses (per thread, within a tile) ----
    // A: quad q = lane>>3 selects (row-half, k-half); i = lane&7 row in block
    const int q  = lane >> 3, qi = lane & 7;
    const uint32_t a_off = (uint32_t)((wm * 64 + (q & 1) * 8 + qi) * LDSW
                                      + (q >> 1) * 4) * 4;
    // B: threads 0-15 supply addresses (k-half q2, row qi); 16-31 mirror them
    const int q2 = (lane >> 3) & 1;
    const uint32_t b_off = (uint32_t)((wn * 32 + qi) * LDSW + q2 * 4) * 4;

    float acc[4][4][4];
    #pragma unroll
    for (int mt = 0; mt < 4; mt++)
        #pragma unroll
        for (int nt = 0; nt < 4; nt++)
            #pragma unroll
            for (int e = 0; e < 4; e++) acc[mt][nt][e] = 0.f;

    const int KCN = K / BK;
    float4 ra[4], rb[4];

    // prologue: load + stage chunk 0 into buffer 0
    #pragma unroll
    for (int i = 0; i < 4; i++) {
        ra[i] = *(const float4*)(Ag + (size_t)(32 * i) * K);
        rb[i] = *(const float4*)(Bg + (size_t)(32 * i) * K);
    }
    #pragma unroll
    for (int i = 0; i < 4; i++) {
        st4_tf32(smem0 + sts_off + i * (32 * LDSW * 4), ra[i]);
        st4_tf32(smem0 + TILE_F * 4 + sts_off + i * (32 * LDSW * 4), rb[i]);
    }
    __syncthreads();

    for (int kc = 0; kc < KCN; kc++) {
        const int buf = kc & 1;
        const uint32_t base = smem0 + (uint32_t)buf * (2 * TILE_F * 4);

        if (kc + 1 < KCN) {             // prefetch next chunk into regs
            const int k0 = (kc + 1) * BK;
            #pragma unroll
            for (int i = 0; i < 4; i++) {
                ra[i] = *(const float4*)(Ag + (size_t)(32 * i) * K + k0);
                rb[i] = *(const float4*)(Bg + (size_t)(32 * i) * K + k0);
            }
        }

        // ---- compute 4 K-steps from buffer ----
        #pragma unroll
        for (int ks = 0; ks < 4; ks++) {
            uint32_t af[4][4], bf[4][2];
            #pragma unroll
            for (int mt = 0; mt < 4; mt++)
                ldsm_x4(af[mt], base + a_off + (uint32_t)(mt * 16 * LDSW * 4 + ks * 32));
            #pragma unroll
            for (int nt = 0; nt < 4; nt++)
                ldsm_x2(bf[nt], base + TILE_F * 4 + b_off
                                + (uint32_t)(nt * 8 * LDSW * 4 + ks * 32));
            #pragma unroll
            for (int mt = 0; mt < 4; mt++)
                #pragma unroll
                for (int nt = 0; nt < 4; nt++)
                    mma_tf32(acc[mt][nt], af[mt], bf[nt]);
        }

        if (kc + 1 < KCN) {             // stage next chunk into other buffer
            const uint32_t nbase = smem0 + (uint32_t)(buf ^ 1) * (2 * TILE_F * 4);
            #pragma unroll
            for (int i = 0; i < 4; i++) {
                st4_tf32(nbase + sts_off + i * (32 * LDSW * 4), ra[i]);
                st4_tf32(nbase + TILE_F * 4 + sts_off + i * (32 * LDSW * 4), rb[i]);
            }
        }
        __syncthreads();
    }

    // ---- epilogue: fragment (t/4, 2*(t%4)) mapping, fused bias/residual ----
    const int er = lane >> 2;           // 0..7
    const int ec = (lane & 3) * 2;      // 0,2,4,6
    #pragma unroll
    for (int mt = 0; mt < 4; mt++) {
        const int r_ = row0 + wm * 64 + mt * 16 + er;
        #pragma unroll
        for (int nt = 0; nt < 4; nt++) {
            const int c_ = col0 + wn * 32 + nt * 8 + ec;
            float2 v0 = make_float2(acc[mt][nt][0], acc[mt][nt][1]);
            float2 v1 = make_float2(acc[mt][nt][2], acc[mt][nt][3]);
            if (bias) {
                float2 bv = *(const float2*)(bias + c_);
                v0.x += bv.x; v0.y += bv.y; v1.x += bv.x; v1.y += bv.y;
            }
            if (res) {
                float2 r0v = *(const float2*)(res + (size_t)r_ * N + c_);
                float2 r1v = *(const float2*)(res + (size_t)(r_ + 8) * N + c_);
                v0.x += r0v.x; v0.y += r0v.y; v1.x += r1v.x; v1.y += r1v.y;
            }
            *(float2*)(C + (size_t)r_ * N + c_)       = v0;
            *(float2*)(C + (size_t)(r_ + 8) * N + c_) = v1;
        }
    }
}

// ---------------- LayerNorm: one block (128 thr) per row of 512 -------------
__global__ void ln_k(const float* __restrict__ x, const float* __restrict__ g,
                     const float* __restrict__ beta, float* __restrict__ y)
{
    __shared__ float red[8];
    const int row = blockIdx.x, tid = threadIdx.x;  // 128 threads, 4 floats each
    float4 v = ((const float4*)(x + (size_t)row*Cs))[tid];
    float s = v.x+v.y+v.z+v.w;
    float q = v.x*v.x+v.y*v.y+v.z*v.z+v.w*v.w;
    #pragma unroll
    for (int o = 16; o; o >>= 1) {
        s += __shfl_xor_sync(0xffffffffu, s, o);
        q += __shfl_xor_sync(0xffffffffu, q, o);
    }
    const int w = tid >> 5;
    if ((tid & 31) == 0) { red[w] = s; red[4+w] = q; }
    __syncthreads();
    s = red[0]+red[1]+red[2]+red[3];
    q = red[4]+red[5]+red[6]+red[7];
    const float mu  = s * (1.f/Cs);
    const float var = q * (1.f/Cs) - mu*mu;
    const float rinv = rsqrtf(var + 1e-5f);
    float4 gg = ((const float4*)g)[tid];
    float4 bb = ((const float4*)beta)[tid];
    float4 o;
    o.x = (v.x-mu)*rinv*gg.x + bb.x;
    o.y = (v.y-mu)*rinv*gg.y + bb.y;
    o.z = (v.z-mu)*rinv*gg.z + bb.z;
    o.w = (v.w-mu)*rinv*gg.w + bb.w;
    ((float4*)(y + (size_t)row*Cs))[tid] = o;
}

// ---------------- Flash attention: per (b,h, 32-query tile), KV tiles of 64 -
__global__ __launch_bounds__(128) void flash_k(const float* __restrict__ qkv,
                                               float* __restrict__ out)
{
    __shared__ __align__(16) float Qs[32][64];
    __shared__ __align__(16) float KtPs[64][68];   // K^T during S; P tile after
    __shared__ __align__(16) float Vs[64][64];

    const int tid = threadIdx.x;
    const int tx = tid & 15, ty = tid >> 4;
    const int bh = blockIdx.y, b = bh >> 3, h = bh & 7;
    const int qi0 = blockIdx.x * 32;
    const float* base = qkv + (size_t)b * Ns * 1536 + h * 192;

    #pragma unroll
    for (int i = 0; i < 4; i++) {       // load Q tile (32x64)
        const int slot = tid + i * 128;
        const int r = slot >> 4, c4 = (slot & 15) * 4;
        *(float4*)&Qs[r][c4] = *(const float4*)(base + (size_t)(qi0 + r) * 1536 + c4);
    }

    float m_r[4], l_r[4], acc[4][4];
    #pragma unroll
    for (int i = 0; i < 4; i++) {
        m_r[i] = -1e30f; l_r[i] = 0.f;
        #pragma unroll
        for (int j = 0; j < 4; j++) acc[i][j] = 0.f;
    }

    for (int j0 = 0; j0 < Ns; j0 += 64) {
        __syncthreads();                 // prev PV done; also covers Q load (iter 0)
        #pragma unroll
        for (int i = 0; i < 8; i++) {    // load K (transposed) + V tiles (64x64)
            const int slot = tid + i * 128;
            const int r = slot >> 4, c4 = (slot & 15) * 4;
            const float* krow = base + (size_t)(j0 + r) * 1536 + 64;
            float4 kv = *(const float4*)(krow + c4);
            KtPs[c4+0][r] = kv.x; KtPs[c4+1][r] = kv.y;
            KtPs[c4+2][r] = kv.z; KtPs[c4+3][r] = kv.w;
            *(float4*)&Vs[r][c4] = *(const float4*)(krow + 64 + c4);
        }
        __syncthreads();

        float s[4][4];
        #pragma unroll
        for (int i = 0; i < 4; i++)
            #pragma unroll
            for (int j = 0; j < 4; j++) s[i][j] = 0.f;
        #pragma unroll 8
        for (int dk = 0; dk < 64; dk++) {
            float4 bq = *(const float4*)&KtPs[dk][tx*4];
            float aq[4];
            #pragma unroll
            for (int i = 0; i < 4; i++) aq[i] = Qs[ty*4+i][dk];
            #pragma unroll
            for (int i = 0; i < 4; i++) {
                s[i][0] = fmaf(aq[i], bq.x, s[i][0]);
                s[i][1] = fmaf(aq[i], bq.y, s[i][1]);
                s[i][2] = fmaf(aq[i], bq.z, s[i][2]);
                s[i][3] = fmaf(aq[i], bq.w, s[i][3]);
            }
        }

        #pragma unroll
        for (int i = 0; i < 4; i++) {
            float mloc = -1e30f;
            #pragma unroll
            for (int j = 0; j < 4; j++) { s[i][j] *= 0.125f; mloc = fmaxf(mloc, s[i][j]); }
            #pragma unroll
            for (int o = 8; o; o >>= 1) mloc = fmaxf(mloc, __shfl_xor_sync(0xffffffffu, mloc, o));
            const float mnew = fmaxf(m_r[i], mloc);
            const float alpha = __expf(m_r[i] - mnew);
            m_r[i] = mnew;
            float ls = 0.f;
            #pragma unroll
            for (int j = 0; j < 4; j++) { s[i][j] = __expf(s[i][j] - mnew); ls += s[i][j]; }
            #pragma unroll
            for (int o = 8; o; o >>= 1) ls += __shfl_xor_sync(0xffffffffu, ls, o);
            l_r[i] = l_r[i] * alpha + ls;
            #pragma unroll
            for (int j = 0; j < 4; j++) acc[i][j] *= alpha;
        }

        __syncthreads();                 // everyone done reading K^T
        float* Ps = &KtPs[0][0];         // reuse as P[32][64]
        #pragma unroll
        for (int i = 0; i < 4; i++)
            *(float4*)&Ps[(ty*4+i)*64 + tx*4] = make_float4(s[i][0], s[i][1], s[i][2], s[i][3]);
        __syncthreads();

        #pragma unroll 8
        for (int kj = 0; kj < 64; kj++) {
            float4 vv = *(const float4*)&Vs[kj][tx*4];
            float pv[4];
            #pragma unroll
            for (int i = 0; i < 4; i++) pv[i] = Ps[(ty*4+i)*64 + kj];
            #pragma unroll
            for (int i = 0; i < 4; i++) {
                acc[i][0] = fmaf(pv[i], vv.x, acc[i][0]);
                acc[i][1] = fmaf(pv[i], vv.y, acc[i][1]);
                acc[i][2] = fmaf(pv[i], vv.z, acc[i][2]);
                acc[i][3] = fmaf(pv[i], vv.w, acc[i][3]);
            }
        }
    }

    #pragma unroll
    for (int i = 0; i < 4; i++) {
        const float inv = 1.f / l_r[i];
        float4 o = make_float4(acc[i][0]*inv, acc[i][1]*inv, acc[i][2]*inv, acc[i][3]*inv);
        *(float4*)(out + (size_t)(b*Ns + qi0 + ty*4 + i) * Cs + h*64 + tx*4) = o;
    }
}

// ---------------- depthwise 3x3 conv + bias + exact GELU --------------------
__global__ void dwconv_gelu_k(const float* __restrict__ hin, const float* __restrict__ w,
                              const float* __restrict__ bias, float* __restrict__ out)
{
    const int bn = blockIdx.x;
    const int b = bn >> 10, n = bn & 1023;
    const int y = n >> 5, x = n & 31;
    const int tid = threadIdx.x;     // 256 threads
    #pragma unroll
    for (int gidx = 0; gidx < 2; gidx++) {
        const int c = (tid + gidx*256) * 4;
        float4 acc = *(const float4*)(bias + c);
        #pragma unroll
        for (int dy = -1; dy <= 1; dy++) {
            const int yy = y + dy;
            if ((unsigned)yy >= 32u) continue;
            #pragma unroll
            for (int dx = -1; dx <= 1; dx++) {
                const int xx = x + dx;
                if ((unsigned)xx >= 32u) continue;
                const float* hp = hin + ((size_t)(b << 10) + (yy << 5) + xx) * HIDs + c;
                float4 hv = *(const float4*)hp;
                const int t = (dy+1)*3 + (dx+1);
                acc.x = fmaf(hv.x, w[(c+0)*9 + t], acc.x);
                acc.y = fmaf(hv.y, w[(c+1)*9 + t], acc.y);
                acc.z = fmaf(hv.z, w[(c+2)*9 + t], acc.z);
                acc.w = fmaf(hv.w, w[(c+3)*9 + t], acc.w);
            }
        }
        float4 o;
        o.x = 0.5f*acc.x*(1.f + erff(acc.x*0.70710678118654752f));
        o.y = 0.5f*acc.y*(1.f + erff(acc.y*0.70710678118654752f));
        o.z = 0.5f*acc.z*(1.f + erff(acc.z*0.70710678118654752f));
        o.w = 0.5f*acc.w*(1.f + erff(acc.w*0.70710678118654752f));
        *(float4*)(out + (size_t)bn*HIDs + c) = o;
    }
}

// ---------------- launch ----------------------------------------------------
extern "C" void kernel_launch(void* const* d_in, const int* in_sizes, int n_in,
                              void* d_out, int out_size)
{
    const float* x      = (const float*)d_in[0];
    const float* ln1_g  = (const float*)d_in[1];
    const float* ln1_b  = (const float*)d_in[2];
    const float* qkv_w  = (const float*)d_in[3];
    const float* proj_w = (const float*)d_in[4];
    const float* proj_b = (const float*)d_in[5];
    const float* ln2_g  = (const float*)d_in[6];
    const float* ln2_b  = (const float*)d_in[7];
    const float* fc1_w  = (const float*)d_in[8];
    const float* fc1_b  = (const float*)d_in[9];
    const float* dw_w   = (const float*)d_in[10];
    const float* dw_b   = (const float*)d_in[11];
    const float* fc2_w  = (const float*)d_in[12];
    const float* fc2_b  = (const float*)d_in[13];
    float* out = (float*)d_out;

    float *xn, *qkv, *att, *h1, *h2;
    cudaGetSymbolAddress((void**)&xn,  g_xn);
    cudaGetSymbolAddress((void**)&qkv, g_qkv);
    cudaGetSymbolAddress((void**)&att, g_att);
    cudaGetSymbolAddress((void**)&h1,  g_h1);
    cudaGetSymbolAddress((void**)&h2,  g_h2);

    cudaFuncSetAttribute(gemm_mma, cudaFuncAttributeMaxDynamicSharedMemorySize, GSMEM);

    // x1 (post-attention residual) lives in d_out; final result overwrites it.
    ln_k<<<Ms, 128>>>(x, ln1_g, ln1_b, xn);
    gemm_mma<<<dim3(1536/128, Ms/128), 256, GSMEM>>>(xn, qkv_w, nullptr, nullptr, qkv, Ms, 1536, Cs);
    flash_k<<<dim3(Ns/32, Bsz*8), 128>>>(qkv, att);
    gemm_mma<<<dim3(Cs/128, Ms/128), 256, GSMEM>>>(att, proj_w, proj_b, x, out, Ms, Cs, Cs);
    ln_k<<<Ms, 128>>>(out, ln2_g, ln2_b, xn);
    gemm_mma<<<dim3(HIDs/128, Ms/128), 256, GSMEM>>>(xn, fc1_w, fc1_b, nullptr, h1, Ms, HIDs, Cs);
    dwconv_gelu_k<<<Ms, 256>>>(h1, dw_w, dw_b, h2);
    gemm_mma<<<dim3(Cs/128, Ms/128), 256, GSMEM>>>(h2, fc2_w, fc2_b, out, out, Ms, Cs, HIDs);
}

// round 16
// speedup vs baseline: 2.8744x; 1.6112x over previous
#include <cuda_runtime.h>
#include <cuda_bf16.h>
#include <cstdint>

#define Bsz 8
#define Ns  1024
#define Cs  512
#define HIDs 2048
#define Ms  (Bsz*Ns)

// ---------------- scratch (device globals; no allocations allowed) ----------
__device__ __align__(16) float g_xn [(size_t)Ms*Cs];        // LN output
__device__ __align__(16) float g_qkv[(size_t)Ms*3*Cs];      // qkv
__device__ __align__(16) float g_att[(size_t)Ms*Cs];        // attention output (pre-proj)
__device__ __align__(16) float g_h1 [(size_t)Ms*HIDs];      // fc1 output
__device__ __align__(16) float g_h2 [(size_t)Ms*HIDs];      // dwconv+gelu output

// ======================= PTX helpers (arch-neutral) =========================
__device__ __forceinline__ uint32_t smem_u32(const void* p) {
    uint32_t a;
    asm("{ .reg .u64 t; cvta.to.shared.u64 t, %1; cvt.u32.u64 %0, t; }" : "=r"(a) : "l"(p));
    return a;
}

__device__ __forceinline__ void st4_tf32(uint32_t saddr, float4 v)
{
    uint32_t a, b, c, d;
    asm("cvt.rna.tf32.f32 %0, %1;" : "=r"(a) : "f"(v.x));
    asm("cvt.rna.tf32.f32 %0, %1;" : "=r"(b) : "f"(v.y));
    asm("cvt.rna.tf32.f32 %0, %1;" : "=r"(c) : "f"(v.z));
    asm("cvt.rna.tf32.f32 %0, %1;" : "=r"(d) : "f"(v.w));
    asm volatile("st.shared.v4.b32 [%0], {%1, %2, %3, %4};"
        :: "r"(saddr), "r"(a), "r"(b), "r"(c), "r"(d) : "memory");
}
__device__ __forceinline__ void st1_tf32(uint32_t saddr, float v)
{
    uint32_t a;
    asm("cvt.rna.tf32.f32 %0, %1;" : "=r"(a) : "f"(v));
    asm volatile("st.shared.b32 [%0], %1;" :: "r"(saddr), "r"(a) : "memory");
}
__device__ __forceinline__ void st2_tf32(uint32_t saddr, float x, float y)
{
    uint32_t a, b;
    asm("cvt.rna.tf32.f32 %0, %1;" : "=r"(a) : "f"(x));
    asm("cvt.rna.tf32.f32 %0, %1;" : "=r"(b) : "f"(y));
    asm volatile("st.shared.v2.b32 [%0], {%1, %2};" :: "r"(saddr), "r"(a), "r"(b) : "memory");
}

__device__ __forceinline__ void ldsm_x4(uint32_t* r, uint32_t addr)
{
    asm volatile("ldmatrix.sync.aligned.m8n8.x4.shared.b16 {%0,%1,%2,%3}, [%4];"
        : "=r"(r[0]), "=r"(r[1]), "=r"(r[2]), "=r"(r[3]) : "r"(addr));
}
__device__ __forceinline__ void ldsm_x2(uint32_t* r, uint32_t addr)
{
    asm volatile("ldmatrix.sync.aligned.m8n8.x2.shared.b16 {%0,%1}, [%2];"
        : "=r"(r[0]), "=r"(r[1]) : "r"(addr));
}

__device__ __forceinline__ void mma_tf32(float* c, const uint32_t* a, const uint32_t* b)
{
    asm volatile("mma.sync.aligned.m16n8k8.row.col.f32.tf32.tf32.f32 "
        "{%0,%1,%2,%3}, {%4,%5,%6,%7}, {%8,%9}, {%0,%1,%2,%3};"
        : "+f"(c[0]), "+f"(c[1]), "+f"(c[2]), "+f"(c[3])
        : "r"(a[0]), "r"(a[1]), "r"(a[2]), "r"(a[3]), "r"(b[0]), "r"(b[1]));
}

// ======================= mma.sync tf32 NT GEMM (unchanged) ==================
#define BK     32
#define LDSW   36
#define TILE_F (128*LDSW)
#define GSMEM  (4*TILE_F*4)

__global__ __launch_bounds__(256) void gemm_mma(
    const float* __restrict__ A, const float* __restrict__ Bw,
    const float* __restrict__ bias, const float* __restrict__ res,
    float* __restrict__ C, int M, int N, int K)
{
    extern __shared__ float sm[];
    const int tid  = threadIdx.x;
    const int lane = tid & 31;
    const int w    = tid >> 5;
    const int wm   = w >> 2;
    const int wn   = w & 3;
    const int row0 = blockIdx.y * 128, col0 = blockIdx.x * 128;

    const int lr = tid >> 3;
    const int lj = tid & 7;
    const float* Ag = A  + (size_t)(row0 + lr) * K + lj * 4;
    const float* Bg = Bw + (size_t)(col0 + lr) * K + lj * 4;

    const uint32_t smem0 = smem_u32(sm);
    const uint32_t sts_off = (uint32_t)(lr * LDSW + lj * 4) * 4;

    const int q  = lane >> 3, qi = lane & 7;
    const uint32_t a_off = (uint32_t)((wm * 64 + (q & 1) * 8 + qi) * LDSW
                                      + (q >> 1) * 4) * 4;
    const int q2 = (lane >> 3) & 1;
    const uint32_t b_off = (uint32_t)((wn * 32 + qi) * LDSW + q2 * 4) * 4;

    float acc[4][4][4];
    #pragma unroll
    for (int mt = 0; mt < 4; mt++)
        #pragma unroll
        for (int nt = 0; nt < 4; nt++)
            #pragma unroll
            for (int e = 0; e < 4; e++) acc[mt][nt][e] = 0.f;

    const int KCN = K / BK;
    float4 ra[4], rb[4];

    #pragma unroll
    for (int i = 0; i < 4; i++) {
        ra[i] = *(const float4*)(Ag + (size_t)(32 * i) * K);
        rb[i] = *(const float4*)(Bg + (size_t)(32 * i) * K);
    }
    #pragma unroll
    for (int i = 0; i < 4; i++) {
        st4_tf32(smem0 + sts_off + i * (32 * LDSW * 4), ra[i]);
        st4_tf32(smem0 + TILE_F * 4 + sts_off + i * (32 * LDSW * 4), rb[i]);
    }
    __syncthreads();

    for (int kc = 0; kc < KCN; kc++) {
        const int buf = kc & 1;
        const uint32_t base = smem0 + (uint32_t)buf * (2 * TILE_F * 4);

        if (kc + 1 < KCN) {
            const int k0 = (kc + 1) * BK;
            #pragma unroll
            for (int i = 0; i < 4; i++) {
                ra[i] = *(const float4*)(Ag + (size_t)(32 * i) * K + k0);
                rb[i] = *(const float4*)(Bg + (size_t)(32 * i) * K + k0);
            }
        }

        #pragma unroll
        for (int ks = 0; ks < 4; ks++) {
            uint32_t af[4][4], bf[4][2];
            #pragma unroll
            for (int mt = 0; mt < 4; mt++)
                ldsm_x4(af[mt], base + a_off + (uint32_t)(mt * 16 * LDSW * 4 + ks * 32));
            #pragma unroll
            for (int nt = 0; nt < 4; nt++)
                ldsm_x2(bf[nt], base + TILE_F * 4 + b_off
                                + (uint32_t)(nt * 8 * LDSW * 4 + ks * 32));
            #pragma unroll
            for (int mt = 0; mt < 4; mt++)
                #pragma unroll
                for (int nt = 0; nt < 4; nt++)
                    mma_tf32(acc[mt][nt], af[mt], bf[nt]);
        }

        if (kc + 1 < KCN) {
            const uint32_t nbase = smem0 + (uint32_t)(buf ^ 1) * (2 * TILE_F * 4);
            #pragma unroll
            for (int i = 0; i < 4; i++) {
                st4_tf32(nbase + sts_off + i * (32 * LDSW * 4), ra[i]);
                st4_tf32(nbase + TILE_F * 4 + sts_off + i * (32 * LDSW * 4), rb[i]);
            }
        }
        __syncthreads();
    }

    const int er = lane >> 2;
    const int ec = (lane & 3) * 2;
    #pragma unroll
    for (int mt = 0; mt < 4; mt++) {
        const int r_ = row0 + wm * 64 + mt * 16 + er;
        #pragma unroll
        for (int nt = 0; nt < 4; nt++) {
            const int c_ = col0 + wn * 32 + nt * 8 + ec;
            float2 v0 = make_float2(acc[mt][nt][0], acc[mt][nt][1]);
            float2 v1 = make_float2(acc[mt][nt][2], acc[mt][nt][3]);
            if (bias) {
                float2 bv = *(const float2*)(bias + c_);
                v0.x += bv.x; v0.y += bv.y; v1.x += bv.x; v1.y += bv.y;
            }
            if (res) {
                float2 r0v = *(const float2*)(res + (size_t)r_ * N + c_);
                float2 r1v = *(const float2*)(res + (size_t)(r_ + 8) * N + c_);
                v0.x += r0v.x; v0.y += r0v.y; v1.x += r1v.x; v1.y += r1v.y;
            }
            *(float2*)(C + (size_t)r_ * N + c_)       = v0;
            *(float2*)(C + (size_t)(r_ + 8) * N + c_) = v1;
        }
    }
}

// ======================= mma.sync tf32 flash attention ======================
// Block = (b, h, 64-query tile); 4 warps, warp = 16 q rows. KV tiles of 64.
// Smem: K[64][68] (B-op for S), V^T[64 rows(d)][72] with 16B-granule XOR
// swizzle (B-op for PV; 288B rows keep ldmatrix 16B-aligned), P/Q[64][68].
// V^T element (kv,d) at word d*72 + ((kv>>2) ^ ((d>>2)&7))*4 + (kv&3).
#define FSTR_K 68
#define FSTR_V 72
#define FSTR_P 68
#define FSM_V  (64*FSTR_K)
#define FSM_P  (FSM_V + 64*FSTR_V)
#define FSMEM  ((FSM_P + 64*FSTR_P)*4)

__global__ __launch_bounds__(128) void flash_mma(const float* __restrict__ qkv,
                                                 float* __restrict__ out)
{
    extern __shared__ float fsm[];
    const int tid = threadIdx.x, lane = tid & 31, w = tid >> 5;
    const int bh = blockIdx.y, b = bh >> 3, h = bh & 7;
    const int qi0 = blockIdx.x * 64;
    const float* base = qkv + (size_t)b * Ns * 1536 + h * 192;

    const uint32_t s0 = smem_u32(fsm);
    const uint32_t Kb = s0, Vb = s0 + FSM_V * 4, Pb = s0 + FSM_P * 4;

    const int q  = lane >> 3, qi = lane & 7, q2 = q & 1;
    const int m0 = w * 16;
    const uint32_t a_off  = (uint32_t)((m0 + (q & 1) * 8 + qi) * FSTR_P + (q >> 1) * 4) * 4;
    const uint32_t bk_off = (uint32_t)(qi * FSTR_K + q2 * 4) * 4;

    // gmem staging map: 16 threads/row, 8 passes of 8 rows
    const int gr = tid >> 4, gc = (tid & 15) * 4;

    // ---- load Q tile into P region (tf32), extract A fragments to regs ----
    #pragma unroll
    for (int i = 0; i < 8; i++) {
        const int r = gr + 8 * i;
        float4 v = *(const float4*)(base + (size_t)(qi0 + r) * 1536 + gc);
        st4_tf32(Pb + (uint32_t)(r * FSTR_P + gc) * 4, v);
    }
    __syncthreads();
    uint32_t afq[8][4];
    #pragma unroll
    for (int ks = 0; ks < 8; ks++)
        ldsm_x4(afq[ks], Pb + a_off + ks * 32);

    // ---- per-thread softmax state (rows m0+er, m0+er+8) ----
    float m_r0 = -1e30f, m_r1 = -1e30f, l0 = 0.f, l1 = 0.f;
    float o[8][4];
    #pragma unroll
    for (int nt = 0; nt < 8; nt++)
        #pragma unroll
        for (int e = 0; e < 4; e++) o[nt][e] = 0.f;

    const int er = lane >> 2, ec = (lane & 3) * 2;

    for (int j0 = 0; j0 < Ns; j0 += 64) {
        __syncthreads();                 // K/V reuse: prior S/PV reads done
        #pragma unroll
        for (int i = 0; i < 8; i++) {    // K tile [kv][d] + swizzled V^T tile
            const int r = gr + 8 * i;
            const float* krow = base + (size_t)(j0 + r) * 1536 + 64;
            float4 kv = *(const float4*)(krow + gc);
            st4_tf32(Kb + (uint32_t)(r * FSTR_K + gc) * 4, kv);
            float4 vv = *(const float4*)(krow + 64 + gc);
            const int rg = r >> 2, rw = r & 3;
            float vvb[4] = {vv.x, vv.y, vv.z, vv.w};
            #pragma unroll
            for (int jj = 0; jj < 4; jj++) {
                const int d = gc + jj;
                const uint32_t g = (uint32_t)(rg ^ ((d >> 2) & 7));
                st1_tf32(Vb + (uint32_t)(d * FSTR_V + g * 4 + rw) * 4, vvb[jj]);
            }
        }
        __syncthreads();

        // ---- S = Q K^T (warp: 16 x 64) ----
        float s[8][4];
        #pragma unroll
        for (int nt = 0; nt < 8; nt++)
            #pragma unroll
            for (int e = 0; e < 4; e++) s[nt][e] = 0.f;
        #pragma unroll
        for (int ks = 0; ks < 8; ks++) {
            #pragma unroll
            for (int nt = 0; nt < 8; nt++) {
                uint32_t bf[2];
                ldsm_x2(bf, Kb + bk_off + (uint32_t)(nt * 8 * FSTR_K * 4 + ks * 32));
                mma_tf32(s[nt], afq[ks], bf);
            }
        }

        // ---- online softmax (rows er, er+8 within warp tile) ----
        float rm0 = -1e30f, rm1 = -1e30f;
        #pragma unroll
        for (int nt = 0; nt < 8; nt++) {
            s[nt][0] *= 0.125f; s[nt][1] *= 0.125f;
            s[nt][2] *= 0.125f; s[nt][3] *= 0.125f;
            rm0 = fmaxf(rm0, fmaxf(s[nt][0], s[nt][1]));
            rm1 = fmaxf(rm1, fmaxf(s[nt][2], s[nt][3]));
        }
        rm0 = fmaxf(rm0, __shfl_xor_sync(0xffffffffu, rm0, 1));
        rm0 = fmaxf(rm0, __shfl_xor_sync(0xffffffffu, rm0, 2));
        rm1 = fmaxf(rm1, __shfl_xor_sync(0xffffffffu, rm1, 1));
        rm1 = fmaxf(rm1, __shfl_xor_sync(0xffffffffu, rm1, 2));
        const float mn0 = fmaxf(m_r0, rm0), mn1 = fmaxf(m_r1, rm1);
        const float al0 = __expf(m_r0 - mn0), al1 = __expf(m_r1 - mn1);
        m_r0 = mn0; m_r1 = mn1;
        float sum0 = 0.f, sum1 = 0.f;
        #pragma unroll
        for (int nt = 0; nt < 8; nt++) {
            float p0 = __expf(s[nt][0] - mn0), p1 = __expf(s[nt][1] - mn0);
            float p2 = __expf(s[nt][2] - mn1), p3 = __expf(s[nt][3] - mn1);
            sum0 += p0 + p1; sum1 += p2 + p3;
            const uint32_t pa = Pb + (uint32_t)((m0 + er) * FSTR_P + nt * 8 + ec) * 4;
            st2_tf32(pa, p0, p1);
            st2_tf32(pa + 8 * FSTR_P * 4, p2, p3);
        }
        sum0 += __shfl_xor_sync(0xffffffffu, sum0, 1);
        sum0 += __shfl_xor_sync(0xffffffffu, sum0, 2);
        sum1 += __shfl_xor_sync(0xffffffffu, sum1, 1);
        sum1 += __shfl_xor_sync(0xffffffffu, sum1, 2);
        l0 = l0 * al0 + sum0;
        l1 = l1 * al1 + sum1;
        #pragma unroll
        for (int nt = 0; nt < 8; nt++) {
            o[nt][0] *= al0; o[nt][1] *= al0;
            o[nt][2] *= al1; o[nt][3] *= al1;
        }
        __syncwarp();                    // own-warp P rows visible to ldmatrix

        // ---- O += P V (warp: 16 x 64, k over kv) ----
        #pragma unroll
        for (int ks = 0; ks < 8; ks++) {
            uint32_t af[4];
            ldsm_x4(af, Pb + a_off + ks * 32);
            #pragma unroll
            for (int nt = 0; nt < 8; nt++) {
                const int d = nt * 8 + qi;
                const uint32_t g = (uint32_t)((2 * ks + q2) ^ ((d >> 2) & 7));
                uint32_t bf[2];
                ldsm_x2(bf, Vb + (uint32_t)(d * FSTR_V) * 4 + (g << 4));
                mma_tf32(o[nt], af, bf);
            }
        }
        __syncwarp();                    // P reads done before next overwrite
    }

    const float inv0 = 1.f / l0, inv1 = 1.f / l1;
    #pragma unroll
    for (int nt = 0; nt < 8; nt++) {
        const int r_ = b * Ns + qi0 + m0 + er;
        const int c_ = h * 64 + nt * 8 + ec;
        *(float2*)(out + (size_t)r_ * Cs + c_) =
            make_float2(o[nt][0] * inv0, o[nt][1] * inv0);
        *(float2*)(out + (size_t)(r_ + 8) * Cs + c_) =
            make_float2(o[nt][2] * inv1, o[nt][3] * inv1);
    }
}

// ---------------- LayerNorm: one block (128 thr) per row of 512 -------------
__global__ void ln_k(const float* __restrict__ x, const float* __restrict__ g,
                     const float* __restrict__ beta, float* __restrict__ y)
{
    __shared__ float red[8];
    const int row = blockIdx.x, tid = threadIdx.x;
    float4 v = ((const float4*)(x + (size_t)row*Cs))[tid];
    float s = v.x+v.y+v.z+v.w;
    float q = v.x*v.x+v.y*v.y+v.z*v.z+v.w*v.w;
    #pragma unroll
    for (int o = 16; o; o >>= 1) {
        s += __shfl_xor_sync(0xffffffffu, s, o);
        q += __shfl_xor_sync(0xffffffffu, q, o);
    }
    const int w = tid >> 5;
    if ((tid & 31) == 0) { red[w] = s; red[4+w] = q; }
    __syncthreads();
    s = red[0]+red[1]+red[2]+red[3];
    q = red[4]+red[5]+red[6]+red[7];
    const float mu  = s * (1.f/Cs);
    const float var = q * (1.f/Cs) - mu*mu;
    const float rinv = rsqrtf(var + 1e-5f);
    float4 gg = ((const float4*)g)[tid];
    float4 bb = ((const float4*)beta)[tid];
    float4 o;
    o.x = (v.x-mu)*rinv*gg.x + bb.x;
    o.y = (v.y-mu)*rinv*gg.y + bb.y;
    o.z = (v.z-mu)*rinv*gg.z + bb.z;
    o.w = (v.w-mu)*rinv*gg.w + bb.w;
    ((float4*)(y + (size_t)row*Cs))[tid] = o;
}

// ---------------- depthwise 3x3 conv + bias + exact GELU --------------------
__global__ void dwconv_gelu_k(const float* __restrict__ hin, const float* __restrict__ w,
                              const float* __restrict__ bias, float* __restrict__ out)
{
    const int bn = blockIdx.x;
    const int b = bn >> 10, n = bn & 1023;
    const int y = n >> 5, x = n & 31;
    const int tid = threadIdx.x;
    #pragma unroll
    for (int gidx = 0; gidx < 2; gidx++) {
        const int c = (tid + gidx*256) * 4;
        float4 acc = *(const float4*)(bias + c);
        #pragma unroll
        for (int dy = -1; dy <= 1; dy++) {
            const int yy = y + dy;
            if ((unsigned)yy >= 32u) continue;
            #pragma unroll
            for (int dx = -1; dx <= 1; dx++) {
                const int xx = x + dx;
                if ((unsigned)xx >= 32u) continue;
                const float* hp = hin + ((size_t)(b << 10) + (yy << 5) + xx) * HIDs + c;
                float4 hv = *(const float4*)hp;
                const int t = (dy+1)*3 + (dx+1);
                acc.x = fmaf(hv.x, w[(c+0)*9 + t], acc.x);
                acc.y = fmaf(hv.y, w[(c+1)*9 + t], acc.y);
                acc.z = fmaf(hv.z, w[(c+2)*9 + t], acc.z);
                acc.w = fmaf(hv.w, w[(c+3)*9 + t], acc.w);
            }
        }
        float4 o;
        o.x = 0.5f*acc.x*(1.f + erff(acc.x*0.70710678118654752f));
        o.y = 0.5f*acc.y*(1.f + erff(acc.y*0.70710678118654752f));
        o.z = 0.5f*acc.z*(1.f + erff(acc.z*0.70710678118654752f));
        o.w = 0.5f*acc.w*(1.f + erff(acc.w*0.70710678118654752f));
        *(float4*)(out + (size_t)bn*HIDs + c) = o;
    }
}

// ---------------- launch ----------------------------------------------------
extern "C" void kernel_launch(void* const* d_in, const int* in_sizes, int n_in,
                              void* d_out, int out_size)
{
    const float* x      = (const float*)d_in[0];
    const float* ln1_g  = (const float*)d_in[1];
    const float* ln1_b  = (const float*)d_in[2];
    const float* qkv_w  = (const float*)d_in[3];
    const float* proj_w = (const float*)d_in[4];
    const float* proj_b = (const float*)d_in[5];
    const float* ln2_g  = (const float*)d_in[6];
    const float* ln2_b  = (const float*)d_in[7];
    const float* fc1_w  = (const float*)d_in[8];
    const float* fc1_b  = (const float*)d_in[9];
    const float* dw_w   = (const float*)d_in[10];
    const float* dw_b   = (const float*)d_in[11];
    const float* fc2_w  = (const float*)d_in[12];
    const float* fc2_b  = (const float*)d_in[13];
    float* out = (float*)d_out;

    float *xn, *qkv, *att, *h1, *h2;
    cudaGetSymbolAddress((void**)&xn,  g_xn);
    cudaGetSymbolAddress((void**)&qkv, g_qkv);
    cudaGetSymbolAddress((void**)&att, g_att);
    cudaGetSymbolAddress((void**)&h1,  g_h1);
    cudaGetSymbolAddress((void**)&h2,  g_h2);

    cudaFuncSetAttribute(gemm_mma, cudaFuncAttributeMaxDynamicSharedMemorySize, GSMEM);
    cudaFuncSetAttribute(flash_mma, cudaFuncAttributeMaxDynamicSharedMemorySize, FSMEM);

    ln_k<<<Ms, 128>>>(x, ln1_g, ln1_b, xn);
    gemm_mma<<<dim3(1536/128, Ms/128), 256, GSMEM>>>(xn, qkv_w, nullptr, nullptr, qkv, Ms, 1536, Cs);
    flash_mma<<<dim3(Ns/64, Bsz*8), 128, FSMEM>>>(qkv, att);
    gemm_mma<<<dim3(Cs/128, Ms/128), 256, GSMEM>>>(att, proj_w, proj_b, x, out, Ms, Cs, Cs);
    ln_k<<<Ms, 128>>>(out, ln2_g, ln2_b, xn);
    gemm_mma<<<dim3(HIDs/128, Ms/128), 256, GSMEM>>>(xn, fc1_w, fc1_b, nullptr, h1, Ms, HIDs, Cs);
    dwconv_gelu_k<<<Ms, 256>>>(h1, dw_w, dw_b, h2);
    gemm_mma<<<dim3(Cs/128, Ms/128), 256, GSMEM>>>(h2, fc2_w, fc2_b, out, out, Ms, Cs, HIDs);
}